// round 15
// baseline (speedup 1.0000x reference)
#include <cuda_runtime.h>
#include <cuda_bf16.h>
#include <math.h>
#include <stdint.h>

#define N_NODES 50000
#define E_EDGES 400000
#define TOT_E   (E_EDGES + N_NODES)
#define HID     256
#define HEADS   8
#define KPAD    176   // 165 padded to /16

// ------------------------- scratch (device globals) -------------------------
__device__ float g_h   [N_NODES * HID];          // 51 MB  (ping)
__device__ float g_h2  [N_NODES * HID];          // 51 MB  (pong)
__device__ float g_big [N_NODES * HID * HEADS];  // 410 MB (layer2 agg, [N, 2048])
__device__ float g_xp  [N_NODES * KPAD];         // 35 MB  padded input
__device__ float g_w2p [HID * HEADS * HID];      // 2 MB   permuted w2 (x 1/8)
__device__ float g_cvec[2 * HEADS * HID];        // folded score vectors
__device__ float g_ssrc [N_NODES * HEADS];
__device__ float g_sdst [N_NODES * HEADS];
__device__ float g_ssrc2[N_NODES * HEADS];       // layer-2 scores (fused)
__device__ float g_sdst2[N_NODES * HEADS];
__device__ float g_t1  [N_NODES * 128];
__device__ int   g_deg [N_NODES];
__device__ int   g_fill[N_NODES];
__device__ int   g_rowptr[N_NODES + 1];
__device__ int   g_col [TOT_E];

// ------------------------- CSR build -------------------------
__global__ void k_init_deg(int* deg, int* fill) {
    int i = blockIdx.x * blockDim.x + threadIdx.x;
    if (i < N_NODES) { deg[i] = 1; fill[i] = 0; }   // self-loop counts as 1
}

__global__ void k_hist(const int* __restrict__ dst, int* deg) {
    int i = blockIdx.x * blockDim.x + threadIdx.x;
    if (i < E_EDGES) atomicAdd(&deg[dst[i]], 1);
}

// single-block chunked exclusive scan (n = 50000, cheap)
__global__ void k_scan(const int* __restrict__ deg, int* rowptr) {
    __shared__ int sh[1024];
    __shared__ int soff;
    if (threadIdx.x == 0) soff = 0;
    __syncthreads();
    for (int base = 0; base < N_NODES; base += 1024) {
        int i = base + threadIdx.x;
        int v = (i < N_NODES) ? deg[i] : 0;
        sh[threadIdx.x] = v;
        __syncthreads();
        for (int off = 1; off < 1024; off <<= 1) {
            int t = (threadIdx.x >= off) ? sh[threadIdx.x - off] : 0;
            __syncthreads();
            sh[threadIdx.x] += t;
            __syncthreads();
        }
        if (i < N_NODES) rowptr[i] = soff + sh[threadIdx.x] - v;  // exclusive
        __syncthreads();
        if (threadIdx.x == 1023) soff += sh[1023];
        __syncthreads();
    }
    if (threadIdx.x == 0) rowptr[N_NODES] = soff;
}

__global__ void k_fill(const int* __restrict__ src, const int* __restrict__ dst,
                       const int* __restrict__ rowptr, int* fill, int* col) {
    int i = blockIdx.x * blockDim.x + threadIdx.x;
    if (i >= TOT_E) return;
    int u, v;
    if (i < E_EDGES) { u = src[i]; v = dst[i]; }
    else             { u = v = i - E_EDGES; }
    int pos = rowptr[v] + atomicAdd(&fill[v], 1);
    col[pos] = u;
}

// pad x [N,165] -> xp [N,176] (zero tail)
__global__ void k_padx(const float* __restrict__ x, float* __restrict__ xp) {
    int i = blockIdx.x * blockDim.x + threadIdx.x;
    if (i >= N_NODES * KPAD) return;
    int r = i / KPAD, c = i % KPAD;
    xp[i] = (c < 165) ? x[(size_t)r * 165 + c] : 0.f;
}

// ------------------------- tf32 tensor-core GEMM ---------------------------
// C[M,N] = A[M,K] @ B[K,N] (+bias) (+relu if ACT==1)
// CTA tile 128x128, BK=16, 8 warps (2x4), warp tile 64x32, mma m16n8k8.tf32
// 3-stage cp.async pipeline in DYNAMIC smem (56,064 B/CTA; opt-in attribute).
// SC==1: fused per-head attention scores (head dim 32 == warp n-tile).
__device__ __forceinline__ uint32_t to_tf32(float x) {
    uint32_t r;
    asm("cvt.rna.tf32.f32 %0, %1;" : "=r"(r) : "f"(x));
    return r;
}

__device__ __forceinline__ void cp_async16(const void* smem_dst, const void* gsrc, bool pred) {
    uint32_t d = (uint32_t)__cvta_generic_to_shared(smem_dst);
    int sz = pred ? 16 : 0;
    asm volatile("cp.async.cg.shared.global [%0], [%1], 16, %2;"
                 :: "r"(d), "l"(gsrc), "r"(sz) : "memory");
}
#define CP_COMMIT() asm volatile("cp.async.commit_group;" ::: "memory")

#define AS_STRIDE 20
#define BS_STRIDE 132
#define AS_STAGE  (128 * AS_STRIDE)          // 2560 floats
#define BS_STAGE  (16 * BS_STRIDE)           // 2112 floats
#define SMEM_FLOATS (3 * AS_STAGE + 3 * BS_STAGE)   // 14016 floats = 56064 B

template <int ACT, int SC>
__global__ __launch_bounds__(256)
void sgemm_tc(const float* __restrict__ A, const float* __restrict__ B,
              const float* __restrict__ bias, float* __restrict__ C,
              int M, int N, int K,
              const float* __restrict__ asrc, const float* __restrict__ adst,
              float* __restrict__ ssrc, float* __restrict__ sdst) {
    extern __shared__ float smem[];
    float* AsBase = smem;                    // [3][128][20]
    float* BsBase = smem + 3 * AS_STAGE;     // [3][16][132]

    const int tid  = threadIdx.x;
    const int lane = tid & 31;
    const int wid  = tid >> 5;
    const int wm   = (wid >> 2) * 64;   // warp row base in tile
    const int wn   = (wid & 3) * 32;    // warp col base in tile
    const int row0 = blockIdx.y * 128;
    const int col0 = blockIdx.x * 128;
    const int grp  = lane >> 2;         // 0..7
    const int qid  = lane & 3;          // 0..3

    float c[4][4][4];
#pragma unroll
    for (int i = 0; i < 4; i++)
#pragma unroll
        for (int j = 0; j < 4; j++)
#pragma unroll
            for (int r = 0; r < 4; r++) c[i][j][r] = 0.f;

    const int ar  = tid >> 2;
    const int ac  = (tid & 3) * 4;
    const int br  = tid >> 5;
    const int bc  = (tid & 31) * 4;

    const int nt = K >> 4;

    auto issue = [&](int k0, int s) {
        float* As = AsBase + s * AS_STAGE;
        float* Bs = BsBase + s * BS_STAGE;
#pragma unroll
        for (int half = 0; half < 2; half++) {
            int r = ar + half * 64;
            int gr = row0 + r;
            const float* gp = A + (size_t)(gr < M ? gr : 0) * K + k0 + ac;
            cp_async16(&As[r * AS_STRIDE + ac], gp, gr < M);
        }
#pragma unroll
        for (int half = 0; half < 2; half++) {
            int r = br + half * 8;
            cp_async16(&Bs[r * BS_STRIDE + bc], B + (size_t)(k0 + r) * N + col0 + bc, true);
        }
        CP_COMMIT();
    };

    issue(0, 0);
    if (nt > 1) issue(16, 1);
    int s = 0;
    for (int i = 0; i < nt; i++) {
        if (i + 2 < nt) {
            issue((i + 2) << 4, (i + 2) % 3);
            asm volatile("cp.async.wait_group 2;" ::: "memory");
        } else if (i + 1 < nt) {
            asm volatile("cp.async.wait_group 1;" ::: "memory");
        } else {
            asm volatile("cp.async.wait_group 0;" ::: "memory");
        }
        __syncthreads();

        const float* As = AsBase + s * AS_STAGE;
        const float* Bs = BsBase + s * BS_STAGE;
#pragma unroll
        for (int kk = 0; kk < 2; kk++) {
            const int kb = kk * 8;
            uint32_t a[4][4], b[4][2];
#pragma unroll
            for (int mi = 0; mi < 4; mi++) {
                int m = wm + mi * 16 + grp;
                a[mi][0] = to_tf32(As[m * AS_STRIDE + kb + qid]);
                a[mi][1] = to_tf32(As[(m + 8) * AS_STRIDE + kb + qid]);
                a[mi][2] = to_tf32(As[m * AS_STRIDE + kb + qid + 4]);
                a[mi][3] = to_tf32(As[(m + 8) * AS_STRIDE + kb + qid + 4]);
            }
#pragma unroll
            for (int ni = 0; ni < 4; ni++) {
                int n = wn + ni * 8 + grp;
                b[ni][0] = to_tf32(Bs[(kb + qid) * BS_STRIDE + n]);
                b[ni][1] = to_tf32(Bs[(kb + qid + 4) * BS_STRIDE + n]);
            }
#pragma unroll
            for (int mi = 0; mi < 4; mi++)
#pragma unroll
                for (int ni = 0; ni < 4; ni++) {
                    asm volatile(
                        "mma.sync.aligned.m16n8k8.row.col.f32.tf32.tf32.f32 "
                        "{%0,%1,%2,%3}, {%4,%5,%6,%7}, {%8,%9}, {%0,%1,%2,%3};"
                        : "+f"(c[mi][ni][0]), "+f"(c[mi][ni][1]),
                          "+f"(c[mi][ni][2]), "+f"(c[mi][ni][3])
                        : "r"(a[mi][0]), "r"(a[mi][1]), "r"(a[mi][2]), "r"(a[mi][3]),
                          "r"(b[ni][0]), "r"(b[ni][1]));
                }
        }
        __syncthreads();
        if (++s == 3) s = 0;
    }

    // ---- epilogue: store ----
#pragma unroll
    for (int mi = 0; mi < 4; mi++) {
#pragma unroll
        for (int ni = 0; ni < 4; ni++) {
            int col = col0 + wn + ni * 8 + qid * 2;
            float b0 = bias ? bias[col] : 0.f;
            float b1 = bias ? bias[col + 1] : 0.f;
#pragma unroll
            for (int rh = 0; rh < 2; rh++) {
                int row = row0 + wm + mi * 16 + grp + rh * 8;
                if (row >= M) continue;
                float v0 = c[mi][ni][2 * rh + 0] + b0;
                float v1 = c[mi][ni][2 * rh + 1] + b1;
                if (ACT == 1) { v0 = fmaxf(v0, 0.f); v1 = fmaxf(v1, 0.f); }
                *reinterpret_cast<float2*>(C + (size_t)row * N + col) = make_float2(v0, v1);
            }
        }
    }

    // ---- epilogue: fused per-head scores (warp n-tile == one head of 32) ----
    if constexpr (SC == 1) {
        const int head = (col0 + wn) >> 5;     // 0..7
        float av[8], dv[8];
#pragma unroll
        for (int ni = 0; ni < 4; ni++)
#pragma unroll
            for (int bb = 0; bb < 2; bb++) {
                int d = ni * 8 + qid * 2 + bb;          // 0..31 within head
                av[ni * 2 + bb] = asrc[head * 32 + d];
                dv[ni * 2 + bb] = adst[head * 32 + d];
            }
#pragma unroll
        for (int mi = 0; mi < 4; mi++)
#pragma unroll
            for (int rh = 0; rh < 2; rh++) {
                float s0 = 0.f, s1 = 0.f;
#pragma unroll
                for (int ni = 0; ni < 4; ni++)
#pragma unroll
                    for (int bb = 0; bb < 2; bb++) {
                        float v = c[mi][ni][2 * rh + bb];
                        s0 += v * av[ni * 2 + bb];
                        s1 += v * dv[ni * 2 + bb];
                    }
                s0 += __shfl_xor_sync(0xFFFFFFFFu, s0, 1);
                s1 += __shfl_xor_sync(0xFFFFFFFFu, s1, 1);
                s0 += __shfl_xor_sync(0xFFFFFFFFu, s0, 2);
                s1 += __shfl_xor_sync(0xFFFFFFFFu, s1, 2);
                int row = row0 + wm + mi * 16 + grp + rh * 8;
                if (qid == 0 && row < M) {
                    ssrc[row * HEADS + head] = s0;
                    sdst[row * HEADS + head] = s1;
                }
            }
    }
}

// ------------------------- online-softmax aggregation (layers 0/1) ---------
// Block = one node (8 warps = 8 heads, D=32). SC2==1 (layer 1): additionally
// compute layer-2 scores ssrc2/sdst2 = (elu output row) . cvec[16 vectors],
// fusing k_scores2 (partials per warp, smem-reduced across heads).
template <int SC2>
__global__ __launch_bounds__(256)
void k_aggr(const float* __restrict__ feat,
            const int* __restrict__ rowptr, const int* __restrict__ col,
            const float* __restrict__ ssrc, const float* __restrict__ sdst,
            const float* __restrict__ bias, float* __restrict__ out,
            const float* __restrict__ cvec,
            float* __restrict__ ssrc2, float* __restrict__ sdst2) {
    __shared__ float shp[16][8];
    const int v    = blockIdx.x;        // one node per block
    const int head = threadIdx.x >> 5;
    const int lane = threadIdx.x & 31;

    float acc = 0.f;
    float m = -INFINITY, s = 0.f;
    float sdv = sdst[v * HEADS + head];
    int e0 = rowptr[v], e1 = rowptr[v + 1];
    for (int j = e0; j < e1; j++) {
        int u = col[j];
        float e = ssrc[u * HEADS + head] + sdv;
        e = (e > 0.f) ? e : 0.2f * e;             // leaky relu
        float nm = fmaxf(m, e);
        float corr = __expf(m - nm);
        float p = __expf(e - nm);
        s = s * corr + p;
        acc = acc * corr + p * feat[(size_t)u * HID + head * 32 + lane];
        m = nm;
    }
    float o = acc / s + bias[head * 32 + lane];
    o = (o > 0.f) ? o : (__expf(o) - 1.f);        // elu
    out[(size_t)v * HID + head * 32 + lane] = o;

    if constexpr (SC2 == 1) {
#pragma unroll
        for (int hd = 0; hd < 8; hd++) {
            float p0 = o * cvec[hd * HID + head * 32 + lane];
            float p1 = o * cvec[HEADS * HID + hd * HID + head * 32 + lane];
#pragma unroll
            for (int off = 16; off; off >>= 1) {
                p0 += __shfl_xor_sync(0xFFFFFFFFu, p0, off);
                p1 += __shfl_xor_sync(0xFFFFFFFFu, p1, off);
            }
            if (lane == 0) { shp[hd][head] = p0; shp[8 + hd][head] = p1; }
        }
        __syncthreads();
        int t = threadIdx.x;
        if (t < 16) {
            float sum = 0.f;
#pragma unroll
            for (int h = 0; h < 8; h++) sum += shp[t][h];
            if (t < 8) ssrc2[v * HEADS + t] = sum;
            else       sdst2[v * HEADS + (t - 8)] = sum;
        }
    }
}

// ------------------------- layer-2: folded score vectors -------------------
__global__ void k_cvec(const float* __restrict__ w2,
                       const float* __restrict__ asrc2,
                       const float* __restrict__ adst2,
                       float* __restrict__ cvec) {
    int i = blockIdx.x * blockDim.x + threadIdx.x;   // h*256+k
    if (i >= HEADS * HID) return;
    int h = i >> 8;
    int k = i & 255;
    const float* wrow = w2 + (size_t)k * (HEADS * HID) + h * HID;
    const float* as = asrc2 + h * HID;
    const float* ad = adst2 + h * HID;
    float s0 = 0.f, s1 = 0.f;
    for (int j = 0; j < HID; j++) {
        float w = wrow[j];
        s0 += w * as[j];
        s1 += w * ad[j];
    }
    cvec[i] = s0;
    cvec[HEADS * HID + i] = s1;
}

// ------------------------- layer-2 aggregation: block per node -------------
__global__ __launch_bounds__(256)
void k_aggr2c(const float* __restrict__ feat,
              const int* __restrict__ rowptr, const int* __restrict__ col,
              const float* __restrict__ ssrc, const float* __restrict__ sdst,
              float* __restrict__ out) {
    __shared__ float sp[32][8];    // p per (edge-in-chunk, head)
    __shared__ int   su[32];
    __shared__ float sm[8], ssum[8];

    const int v    = blockIdx.x;
    const int tid  = threadIdx.x;
    const int head = tid >> 5;     // warp id = head
    const int lane = tid & 31;
    const int e0 = rowptr[v], e1 = rowptr[v + 1];
    const float sdv = sdst[v * HEADS + head];

    // ---- pass 1: per-head (m, s) ----
    float m = -INFINITY, s = 0.f;
    for (int j = e0 + lane; j < e1; j += 32) {
        float e = ssrc[col[j] * HEADS + head] + sdv;
        e = (e > 0.f) ? e : 0.2f * e;
        float nm = fmaxf(m, e);
        s = s * __expf(m - nm) + __expf(e - nm);   // m=-inf, nm finite -> exp=0, safe
        m = nm;
    }
#pragma unroll
    for (int o = 16; o; o >>= 1) {
        float m2 = __shfl_xor_sync(0xFFFFFFFFu, m, o);
        float s2 = __shfl_xor_sync(0xFFFFFFFFu, s, o);
        float nm = fmaxf(m, m2);
        // NaN-safe: when m == nm (incl. both -inf), factor is exactly 1.
        float c1 = (m  == nm) ? 1.f : __expf(m  - nm);
        float c2 = (m2 == nm) ? 1.f : __expf(m2 - nm);
        s = s * c1 + s2 * c2;
        m = nm;
    }
    if (lane == 0) { sm[head] = m; ssum[head] = 1.f / s; }
    __syncthreads();

    // ---- pass 2: stream features once per edge ----
    float acc[8];
#pragma unroll
    for (int h = 0; h < 8; h++) acc[h] = 0.f;
    const float mh  = sm[head];
    const float ish = ssum[head];

    for (int base = e0; base < e1; base += 32) {
        int cnt = min(32, e1 - base);
        if (lane < cnt) {
            int u = col[base + lane];
            if (head == 0) su[lane] = u;
            float e = ssrc[u * HEADS + head] + sdv;
            e = (e > 0.f) ? e : 0.2f * e;
            sp[lane][head] = __expf(e - mh) * ish;
        }
        __syncthreads();
        for (int t = 0; t < cnt; t++) {
            float x = feat[(size_t)su[t] * HID + tid];
            float4 p0 = *reinterpret_cast<const float4*>(&sp[t][0]);
            float4 p1 = *reinterpret_cast<const float4*>(&sp[t][4]);
            acc[0] += p0.x * x; acc[1] += p0.y * x;
            acc[2] += p0.z * x; acc[3] += p0.w * x;
            acc[4] += p1.x * x; acc[5] += p1.y * x;
            acc[6] += p1.z * x; acc[7] += p1.w * x;
        }
        __syncthreads();
    }
    size_t ob = (size_t)v * (HEADS * HID) + tid;
#pragma unroll
    for (int h = 0; h < 8; h++) out[ob + h * HID] = acc[h];
}

// permute w2 -> W2p[h*256+k][j] = w2[k][h*256+j] * (1/8)
__global__ void k_permw2(const float* __restrict__ w2, float* __restrict__ w2p) {
    int i = blockIdx.x * blockDim.x + threadIdx.x;   // over 2048*256
    if (i >= HEADS * HID * HID) return;
    int rowp = i >> 8;           // h*256+k
    int j = i & 255;
    int h = rowp >> 8, k = rowp & 255;
    w2p[i] = w2[(size_t)k * (HEADS * HID) + h * HID + j] * 0.125f;
}

// ------------------------- final tiny GEMM (N=2) ---------------------------
__global__ void k_final(const float* __restrict__ t1, const float* __restrict__ wc2,
                        const float* __restrict__ bc2, float* __restrict__ out) {
    __shared__ float w[256];
    if (threadIdx.x < 256) w[threadIdx.x] = wc2[threadIdx.x];
    __syncthreads();
    int row = blockIdx.x * blockDim.x + threadIdx.x;
    if (row >= N_NODES) return;
    float a0 = bc2[0], a1 = bc2[1];
    const float* t = t1 + (size_t)row * 128;
#pragma unroll 8
    for (int k = 0; k < 128; k++) {
        float x = t[k];
        a0 += x * w[2 * k];
        a1 += x * w[2 * k + 1];
    }
    out[row * 2 + 0] = a0;
    out[row * 2 + 1] = a1;
}

// ------------------------- host -------------------------
static inline int cdiv(int a, int b) { return (a + b - 1) / b; }

#define SMEM_BYTES (SMEM_FLOATS * 4)

extern "C" void kernel_launch(void* const* d_in, const int* in_sizes, int n_in,
                              void* d_out, int out_size) {
    const float* x     = (const float*)d_in[0];
    const int*   ei    = (const int*)  d_in[1];   // [2, E]
    const float* w_in  = (const float*)d_in[2];
    const float* b_in  = (const float*)d_in[3];
    const float* w0    = (const float*)d_in[4];
    const float* asrc0 = (const float*)d_in[5];
    const float* adst0 = (const float*)d_in[6];
    const float* b0    = (const float*)d_in[7];
    const float* w1    = (const float*)d_in[8];
    const float* asrc1 = (const float*)d_in[9];
    const float* adst1 = (const float*)d_in[10];
    const float* b1    = (const float*)d_in[11];
    const float* w2    = (const float*)d_in[12];
    const float* asrc2 = (const float*)d_in[13];
    const float* adst2 = (const float*)d_in[14];
    const float* b2    = (const float*)d_in[15];
    const float* wc1   = (const float*)d_in[16];
    const float* bc1   = (const float*)d_in[17];
    const float* wc2   = (const float*)d_in[18];
    const float* bc2   = (const float*)d_in[19];

    const int* src = ei;
    const int* dst = ei + E_EDGES;

    float *p_h, *p_h2, *p_big, *p_xp, *p_w2p, *p_cvec;
    float *p_ssrc, *p_sdst, *p_ssrc2, *p_sdst2, *p_t1;
    int *p_deg, *p_fill, *p_rowptr, *p_col;
    cudaGetSymbolAddress((void**)&p_h, g_h);
    cudaGetSymbolAddress((void**)&p_h2, g_h2);
    cudaGetSymbolAddress((void**)&p_big, g_big);
    cudaGetSymbolAddress((void**)&p_xp, g_xp);
    cudaGetSymbolAddress((void**)&p_w2p, g_w2p);
    cudaGetSymbolAddress((void**)&p_cvec, g_cvec);
    cudaGetSymbolAddress((void**)&p_ssrc, g_ssrc);
    cudaGetSymbolAddress((void**)&p_sdst, g_sdst);
    cudaGetSymbolAddress((void**)&p_ssrc2, g_ssrc2);
    cudaGetSymbolAddress((void**)&p_sdst2, g_sdst2);
    cudaGetSymbolAddress((void**)&p_t1, g_t1);
    cudaGetSymbolAddress((void**)&p_deg, g_deg);
    cudaGetSymbolAddress((void**)&p_fill, g_fill);
    cudaGetSymbolAddress((void**)&p_rowptr, g_rowptr);
    cudaGetSymbolAddress((void**)&p_col, g_col);

    // opt-in to >48KB dynamic smem for all GEMM instantiations (idempotent)
    cudaFuncSetAttribute(sgemm_tc<0, 0>, cudaFuncAttributeMaxDynamicSharedMemorySize, SMEM_BYTES);
    cudaFuncSetAttribute(sgemm_tc<0, 1>, cudaFuncAttributeMaxDynamicSharedMemorySize, SMEM_BYTES);
    cudaFuncSetAttribute(sgemm_tc<1, 0>, cudaFuncAttributeMaxDynamicSharedMemorySize, SMEM_BYTES);

    // ---- CSR build + preprocessing ----
    k_init_deg<<<cdiv(N_NODES, 256), 256>>>(p_deg, p_fill);
    k_hist<<<cdiv(E_EDGES, 256), 256>>>(dst, p_deg);
    k_scan<<<1, 1024>>>(p_deg, p_rowptr);
    k_fill<<<cdiv(TOT_E, 256), 256>>>(src, dst, p_rowptr, p_fill, p_col);
    k_padx<<<cdiv(N_NODES * KPAD, 256), 256>>>(x, p_xp);
    k_cvec<<<cdiv(HEADS * HID, 256), 256>>>(w2, asrc2, adst2, p_cvec);
    k_permw2<<<cdiv(HEADS * HID * HID, 256), 256>>>(w2, p_w2p);

    dim3 blk(256);

    // ---- input projection: h = xp @ w_in + b_in (K padded to 176) ----
    {
        dim3 grid(cdiv(HID, 128), cdiv(N_NODES, 128));
        sgemm_tc<0, 0><<<grid, blk, SMEM_BYTES>>>(p_xp, w_in, b_in, p_h, N_NODES, HID, KPAD,
                                                  nullptr, nullptr, nullptr, nullptr);
    }
    // ---- GAT layer 0 (concat); scores fused into GEMM epilogue ----
    {
        dim3 grid(cdiv(HID, 128), cdiv(N_NODES, 128));
        sgemm_tc<0, 1><<<grid, blk, SMEM_BYTES>>>(p_h, w0, nullptr, p_h2, N_NODES, HID, HID,
                                                  asrc0, adst0, p_ssrc, p_sdst);
        k_aggr<0><<<N_NODES, 256>>>(p_h2, p_rowptr, p_col, p_ssrc, p_sdst, b0, p_h,
                                    nullptr, nullptr, nullptr);
    }
    // ---- GAT layer 1 (concat); scores fused into GEMM epilogue;
    //      layer-2 scores fused into this aggregation (replaces k_scores2) ----
    {
        dim3 grid(cdiv(HID, 128), cdiv(N_NODES, 128));
        sgemm_tc<0, 1><<<grid, blk, SMEM_BYTES>>>(p_h, w1, nullptr, p_h2, N_NODES, HID, HID,
                                                  asrc1, adst1, p_ssrc, p_sdst);
        k_aggr<1><<<N_NODES, 256>>>(p_h2, p_rowptr, p_col, p_ssrc, p_sdst, b1, p_h,
                                    p_cvec, p_ssrc2, p_sdst2);
    }
    // ---- GAT layer 2 (mean heads), aggregation commuted before GEMM ----
    {
        k_aggr2c<<<N_NODES, 256>>>(p_h, p_rowptr, p_col, p_ssrc2, p_sdst2, p_big);
        dim3 grid(cdiv(HID, 128), cdiv(N_NODES, 128));
        sgemm_tc<0, 0><<<grid, blk, SMEM_BYTES>>>(p_big, p_w2p, b2, p_h2, N_NODES, HID, HEADS * HID,
                                                  nullptr, nullptr, nullptr, nullptr);
    }
    // ---- classifier ----
    {
        dim3 grid(1, cdiv(N_NODES, 128));
        sgemm_tc<1, 0><<<grid, blk, SMEM_BYTES>>>(p_h2, wc1, bc1, p_t1, N_NODES, 128, HID,
                                                  nullptr, nullptr, nullptr, nullptr);
        k_final<<<cdiv(N_NODES, 256), 256>>>(p_t1, wc2, bc2, (float*)d_out);
    }
}

// round 16
// speedup vs baseline: 1.0939x; 1.0939x over previous
#include <cuda_runtime.h>
#include <cuda_bf16.h>
#include <math.h>
#include <stdint.h>

#define N_NODES 50000
#define E_EDGES 400000
#define TOT_E   (E_EDGES + N_NODES)
#define HID     256
#define HEADS   8
#define KPAD    176   // 165 padded to /16
#define NBLK    ((N_NODES + 1023) / 1024)   // 49 scan blocks

// ------------------------- scratch (device globals) -------------------------
__device__ float g_h   [N_NODES * HID];          // 51 MB  (ping)
__device__ float g_h2  [N_NODES * HID];          // 51 MB  (pong)
__device__ float g_big [N_NODES * HID * HEADS];  // 410 MB (layer2 agg, [N, 2048])
__device__ float g_xp  [N_NODES * KPAD];         // 35 MB  padded input
__device__ float g_w2p [HID * HEADS * HID];      // 2 MB   permuted w2 (x 1/8)
__device__ float g_cvec[2 * HEADS * HID];        // folded score vectors
__device__ float g_ssrc[N_NODES * HEADS];
__device__ float g_sdst[N_NODES * HEADS];
__device__ float g_t1  [N_NODES * 128];
__device__ int   g_deg [N_NODES];
__device__ int   g_fill[N_NODES];
__device__ int   g_rowptr[N_NODES + 1];
__device__ int   g_col [TOT_E];
__device__ int   g_bsum[64];

// ------------------------- CSR build -------------------------
__global__ void k_init_deg(int* deg, int* fill) {
    int i = blockIdx.x * blockDim.x + threadIdx.x;
    if (i < N_NODES) { deg[i] = 1; fill[i] = 0; }   // self-loop counts as 1
}

__global__ void k_hist(const int* __restrict__ dst, int* deg) {
    int i = blockIdx.x * blockDim.x + threadIdx.x;
    if (i < E_EDGES) atomicAdd(&deg[dst[i]], 1);
}

// parallel 3-phase exclusive scan over deg -> rowptr
__global__ void k_scan1(const int* __restrict__ deg, int* rowptr, int* bsum) {
    __shared__ int sh[1024];
    int i = blockIdx.x * 1024 + threadIdx.x;
    int v = (i < N_NODES) ? deg[i] : 0;
    sh[threadIdx.x] = v;
    __syncthreads();
    for (int off = 1; off < 1024; off <<= 1) {
        int t = (threadIdx.x >= off) ? sh[threadIdx.x - off] : 0;
        __syncthreads();
        sh[threadIdx.x] += t;
        __syncthreads();
    }
    if (i < N_NODES) rowptr[i] = sh[threadIdx.x] - v;   // local exclusive
    if (threadIdx.x == 1023) bsum[blockIdx.x] = sh[1023];
}

__global__ void k_scan2(int* bsum, int* rowptr) {
    int acc = 0;
    for (int b = 0; b < NBLK; b++) { int t = bsum[b]; bsum[b] = acc; acc += t; }
    rowptr[N_NODES] = acc;
}

__global__ void k_scan3(int* rowptr, const int* __restrict__ bsum) {
    int i = blockIdx.x * blockDim.x + threadIdx.x;
    if (i < N_NODES) rowptr[i] += bsum[i >> 10];
}

__global__ void k_fill(const int* __restrict__ src, const int* __restrict__ dst,
                       const int* __restrict__ rowptr, int* fill, int* col) {
    int i = blockIdx.x * blockDim.x + threadIdx.x;
    if (i >= TOT_E) return;
    int u, v;
    if (i < E_EDGES) { u = src[i]; v = dst[i]; }
    else             { u = v = i - E_EDGES; }
    int pos = rowptr[v] + atomicAdd(&fill[v], 1);
    col[pos] = u;
}

// pad x [N,165] -> xp [N,176] (zero tail)
__global__ void k_padx(const float* __restrict__ x, float* __restrict__ xp) {
    int i = blockIdx.x * blockDim.x + threadIdx.x;
    if (i >= N_NODES * KPAD) return;
    int r = i / KPAD, c = i % KPAD;
    xp[i] = (c < 165) ? x[(size_t)r * 165 + c] : 0.f;
}

// ------------------------- tf32 tensor-core GEMM ---------------------------
// C[M,N] = A[M,K] @ B[K,N] (+bias) (+relu if ACT==1)
// CTA tile 128x128, BK=16, 8 warps (2x4), warp tile 64x32, mma m16n8k8.tf32
// 3-stage cp.async pipeline in DYNAMIC smem (56,064 B/CTA; opt-in attribute).
// SC==1: fused per-head attention scores (head dim 32 == warp n-tile).
__device__ __forceinline__ uint32_t to_tf32(float x) {
    uint32_t r;
    asm("cvt.rna.tf32.f32 %0, %1;" : "=r"(r) : "f"(x));
    return r;
}

__device__ __forceinline__ void cp_async16(const void* smem_dst, const void* gsrc, bool pred) {
    uint32_t d = (uint32_t)__cvta_generic_to_shared(smem_dst);
    int sz = pred ? 16 : 0;
    asm volatile("cp.async.cg.shared.global [%0], [%1], 16, %2;"
                 :: "r"(d), "l"(gsrc), "r"(sz) : "memory");
}
#define CP_COMMIT() asm volatile("cp.async.commit_group;" ::: "memory")

#define AS_STRIDE 20
#define BS_STRIDE 132
#define AS_STAGE  (128 * AS_STRIDE)          // 2560 floats
#define BS_STAGE  (16 * BS_STRIDE)           // 2112 floats
#define SMEM_FLOATS (3 * AS_STAGE + 3 * BS_STAGE)   // 14016 floats = 56064 B

template <int ACT, int SC>
__global__ __launch_bounds__(256)
void sgemm_tc(const float* __restrict__ A, const float* __restrict__ B,
              const float* __restrict__ bias, float* __restrict__ C,
              int M, int N, int K,
              const float* __restrict__ asrc, const float* __restrict__ adst,
              float* __restrict__ ssrc, float* __restrict__ sdst) {
    extern __shared__ float smem[];
    float* AsBase = smem;                    // [3][128][20]
    float* BsBase = smem + 3 * AS_STAGE;     // [3][16][132]

    const int tid  = threadIdx.x;
    const int lane = tid & 31;
    const int wid  = tid >> 5;
    const int wm   = (wid >> 2) * 64;   // warp row base in tile
    const int wn   = (wid & 3) * 32;    // warp col base in tile
    const int row0 = blockIdx.y * 128;
    const int col0 = blockIdx.x * 128;
    const int grp  = lane >> 2;         // 0..7
    const int qid  = lane & 3;          // 0..3

    float c[4][4][4];
#pragma unroll
    for (int i = 0; i < 4; i++)
#pragma unroll
        for (int j = 0; j < 4; j++)
#pragma unroll
            for (int r = 0; r < 4; r++) c[i][j][r] = 0.f;

    const int ar  = tid >> 2;
    const int ac  = (tid & 3) * 4;
    const int br  = tid >> 5;
    const int bc  = (tid & 31) * 4;

    const int nt = K >> 4;

    auto issue = [&](int k0, int s) {
        float* As = AsBase + s * AS_STAGE;
        float* Bs = BsBase + s * BS_STAGE;
#pragma unroll
        for (int half = 0; half < 2; half++) {
            int r = ar + half * 64;
            int gr = row0 + r;
            const float* gp = A + (size_t)(gr < M ? gr : 0) * K + k0 + ac;
            cp_async16(&As[r * AS_STRIDE + ac], gp, gr < M);
        }
#pragma unroll
        for (int half = 0; half < 2; half++) {
            int r = br + half * 8;
            cp_async16(&Bs[r * BS_STRIDE + bc], B + (size_t)(k0 + r) * N + col0 + bc, true);
        }
        CP_COMMIT();
    };

    issue(0, 0);
    if (nt > 1) issue(16, 1);
    int s = 0;
    for (int i = 0; i < nt; i++) {
        if (i + 2 < nt) {
            issue((i + 2) << 4, (i + 2) % 3);
            asm volatile("cp.async.wait_group 2;" ::: "memory");
        } else if (i + 1 < nt) {
            asm volatile("cp.async.wait_group 1;" ::: "memory");
        } else {
            asm volatile("cp.async.wait_group 0;" ::: "memory");
        }
        __syncthreads();

        const float* As = AsBase + s * AS_STAGE;
        const float* Bs = BsBase + s * BS_STAGE;
#pragma unroll
        for (int kk = 0; kk < 2; kk++) {
            const int kb = kk * 8;
            uint32_t a[4][4], b[4][2];
#pragma unroll
            for (int mi = 0; mi < 4; mi++) {
                int m = wm + mi * 16 + grp;
                a[mi][0] = to_tf32(As[m * AS_STRIDE + kb + qid]);
                a[mi][1] = to_tf32(As[(m + 8) * AS_STRIDE + kb + qid]);
                a[mi][2] = to_tf32(As[m * AS_STRIDE + kb + qid + 4]);
                a[mi][3] = to_tf32(As[(m + 8) * AS_STRIDE + kb + qid + 4]);
            }
#pragma unroll
            for (int ni = 0; ni < 4; ni++) {
                int n = wn + ni * 8 + grp;
                b[ni][0] = to_tf32(Bs[(kb + qid) * BS_STRIDE + n]);
                b[ni][1] = to_tf32(Bs[(kb + qid + 4) * BS_STRIDE + n]);
            }
#pragma unroll
            for (int mi = 0; mi < 4; mi++)
#pragma unroll
                for (int ni = 0; ni < 4; ni++) {
                    asm volatile(
                        "mma.sync.aligned.m16n8k8.row.col.f32.tf32.tf32.f32 "
                        "{%0,%1,%2,%3}, {%4,%5,%6,%7}, {%8,%9}, {%0,%1,%2,%3};"
                        : "+f"(c[mi][ni][0]), "+f"(c[mi][ni][1]),
                          "+f"(c[mi][ni][2]), "+f"(c[mi][ni][3])
                        : "r"(a[mi][0]), "r"(a[mi][1]), "r"(a[mi][2]), "r"(a[mi][3]),
                          "r"(b[ni][0]), "r"(b[ni][1]));
                }
        }
        __syncthreads();
        if (++s == 3) s = 0;
    }

    // ---- epilogue: store ----
#pragma unroll
    for (int mi = 0; mi < 4; mi++) {
#pragma unroll
        for (int ni = 0; ni < 4; ni++) {
            int col = col0 + wn + ni * 8 + qid * 2;
            float b0 = bias ? bias[col] : 0.f;
            float b1 = bias ? bias[col + 1] : 0.f;
#pragma unroll
            for (int rh = 0; rh < 2; rh++) {
                int row = row0 + wm + mi * 16 + grp + rh * 8;
                if (row >= M) continue;
                float v0 = c[mi][ni][2 * rh + 0] + b0;
                float v1 = c[mi][ni][2 * rh + 1] + b1;
                if (ACT == 1) { v0 = fmaxf(v0, 0.f); v1 = fmaxf(v1, 0.f); }
                *reinterpret_cast<float2*>(C + (size_t)row * N + col) = make_float2(v0, v1);
            }
        }
    }

    // ---- epilogue: fused per-head scores (warp n-tile == one head of 32) ----
    if constexpr (SC == 1) {
        const int head = (col0 + wn) >> 5;     // 0..7
        float av[8], dv[8];
#pragma unroll
        for (int ni = 0; ni < 4; ni++)
#pragma unroll
            for (int bb = 0; bb < 2; bb++) {
                int d = ni * 8 + qid * 2 + bb;          // 0..31 within head
                av[ni * 2 + bb] = asrc[head * 32 + d];
                dv[ni * 2 + bb] = adst[head * 32 + d];
            }
#pragma unroll
        for (int mi = 0; mi < 4; mi++)
#pragma unroll
            for (int rh = 0; rh < 2; rh++) {
                float s0 = 0.f, s1 = 0.f;
#pragma unroll
                for (int ni = 0; ni < 4; ni++)
#pragma unroll
                    for (int bb = 0; bb < 2; bb++) {
                        float v = c[mi][ni][2 * rh + bb];
                        s0 += v * av[ni * 2 + bb];
                        s1 += v * dv[ni * 2 + bb];
                    }
                // reduce across the 4 qid lanes (lane bits 0-1)
                s0 += __shfl_xor_sync(0xFFFFFFFFu, s0, 1);
                s1 += __shfl_xor_sync(0xFFFFFFFFu, s1, 1);
                s0 += __shfl_xor_sync(0xFFFFFFFFu, s0, 2);
                s1 += __shfl_xor_sync(0xFFFFFFFFu, s1, 2);
                int row = row0 + wm + mi * 16 + grp + rh * 8;
                if (qid == 0 && row < M) {
                    ssrc[row * HEADS + head] = s0;
                    sdst[row * HEADS + head] = s1;
                }
            }
    }
}

// ------------------------- online-softmax aggregation (layers 0/1) ---------
template <int D>
__global__ void k_aggr(const float* __restrict__ feat,
                       const int* __restrict__ rowptr, const int* __restrict__ col,
                       const float* __restrict__ ssrc, const float* __restrict__ sdst,
                       const float* __restrict__ bias, float* __restrict__ out) {
    int warp = (blockIdx.x * blockDim.x + threadIdx.x) >> 5;
    int lane = threadIdx.x & 31;
    if (warp >= N_NODES * HEADS) return;
    int v = warp >> 3, head = warp & 7;
    constexpr int R = D / 32;
    float acc[R];
#pragma unroll
    for (int r = 0; r < R; r++) acc[r] = 0.f;
    float m = -INFINITY, s = 0.f;
    float sdv = sdst[v * HEADS + head];
    int e0 = rowptr[v], e1 = rowptr[v + 1];
    for (int j = e0; j < e1; j++) {
        int u = col[j];
        float e = ssrc[u * HEADS + head] + sdv;
        e = (e > 0.f) ? e : 0.2f * e;             // leaky relu
        float nm = fmaxf(m, e);
        float corr = __expf(m - nm);
        float p = __expf(e - nm);
        s = s * corr + p;
        const float* fu = feat + (size_t)u * (HEADS * D) + head * D + lane;
#pragma unroll
        for (int r = 0; r < R; r++) acc[r] = acc[r] * corr + p * fu[r * 32];
        m = nm;
    }
    float inv = 1.f / s;
    size_t ob = (size_t)v * (HEADS * D) + head * D + lane;
#pragma unroll
    for (int r = 0; r < R; r++) {
        float o = acc[r] * inv + bias[head * D + lane + r * 32];
        out[ob + r * 32] = (o > 0.f) ? o : (__expf(o) - 1.f);  // elu
    }
}

// ------------------------- layer-2: folded score vectors -------------------
__global__ void k_cvec(const float* __restrict__ w2,
                       const float* __restrict__ asrc2,
                       const float* __restrict__ adst2,
                       float* __restrict__ cvec) {
    int i = blockIdx.x * blockDim.x + threadIdx.x;   // h*256+k
    if (i >= HEADS * HID) return;
    int h = i >> 8;
    int k = i & 255;
    const float* wrow = w2 + (size_t)k * (HEADS * HID) + h * HID;
    const float* as = asrc2 + h * HID;
    const float* ad = adst2 + h * HID;
    float s0 = 0.f, s1 = 0.f;
    for (int j = 0; j < HID; j++) {
        float w = wrow[j];
        s0 += w * as[j];
        s1 += w * ad[j];
    }
    cvec[i] = s0;
    cvec[HEADS * HID + i] = s1;
}

// layer-2 scores directly from h: one warp per node, 16 dots of length 256
__global__ __launch_bounds__(256)
void k_scores2(const float* __restrict__ h, const float* __restrict__ cvec,
               float* __restrict__ ssrc, float* __restrict__ sdst) {
    __shared__ float sc[2 * HEADS * HID];   // 16 KB
    for (int i = threadIdx.x; i < 2 * HEADS * HID; i += 256) sc[i] = cvec[i];
    __syncthreads();
    int warp = (blockIdx.x * 256 + threadIdx.x) >> 5;
    int lane = threadIdx.x & 31;
    if (warp >= N_NODES) return;
    float x[8];
    const float* hv = h + (size_t)warp * HID + lane;
#pragma unroll
    for (int r = 0; r < 8; r++) x[r] = hv[r * 32];
#pragma unroll
    for (int hd = 0; hd < HEADS; hd++) {
        float s0 = 0.f, s1 = 0.f;
#pragma unroll
        for (int r = 0; r < 8; r++) {
            s0 += x[r] * sc[hd * HID + r * 32 + lane];
            s1 += x[r] * sc[HEADS * HID + hd * HID + r * 32 + lane];
        }
#pragma unroll
        for (int o = 16; o; o >>= 1) {
            s0 += __shfl_xor_sync(0xFFFFFFFFu, s0, o);
            s1 += __shfl_xor_sync(0xFFFFFFFFu, s1, o);
        }
        if (lane == 0) {
            ssrc[warp * HEADS + hd] = s0;
            sdst[warp * HEADS + hd] = s1;
        }
    }
}

// ------------------------- layer-2 aggregation: block per node -------------
__global__ __launch_bounds__(256)
void k_aggr2c(const float* __restrict__ feat,
              const int* __restrict__ rowptr, const int* __restrict__ col,
              const float* __restrict__ ssrc, const float* __restrict__ sdst,
              float* __restrict__ out) {
    __shared__ float sp[32][8];    // p per (edge-in-chunk, head)
    __shared__ int   su[32];
    __shared__ float sm[8], ssum[8];

    const int v    = blockIdx.x;
    const int tid  = threadIdx.x;
    const int head = tid >> 5;     // warp id = head
    const int lane = tid & 31;
    const int e0 = rowptr[v], e1 = rowptr[v + 1];
    const float sdv = sdst[v * HEADS + head];

    // ---- pass 1: per-head (m, s) ----
    float m = -INFINITY, s = 0.f;
    for (int j = e0 + lane; j < e1; j += 32) {
        float e = ssrc[col[j] * HEADS + head] + sdv;
        e = (e > 0.f) ? e : 0.2f * e;
        float nm = fmaxf(m, e);
        s = s * __expf(m - nm) + __expf(e - nm);   // m=-inf, nm finite -> exp=0, safe
        m = nm;
    }
#pragma unroll
    for (int o = 16; o; o >>= 1) {
        float m2 = __shfl_xor_sync(0xFFFFFFFFu, m, o);
        float s2 = __shfl_xor_sync(0xFFFFFFFFu, s, o);
        float nm = fmaxf(m, m2);
        // NaN-safe: when m == nm (incl. both -inf), factor is exactly 1.
        float c1 = (m  == nm) ? 1.f : __expf(m  - nm);
        float c2 = (m2 == nm) ? 1.f : __expf(m2 - nm);
        s = s * c1 + s2 * c2;
        m = nm;
    }
    if (lane == 0) { sm[head] = m; ssum[head] = 1.f / s; }
    __syncthreads();

    // ---- pass 2: stream features once per edge ----
    float acc[8];
#pragma unroll
    for (int h = 0; h < 8; h++) acc[h] = 0.f;
    const float mh  = sm[head];
    const float ish = ssum[head];

    for (int base = e0; base < e1; base += 32) {
        int cnt = min(32, e1 - base);
        if (lane < cnt) {
            int u = col[base + lane];
            if (head == 0) su[lane] = u;
            float e = ssrc[u * HEADS + head] + sdv;
            e = (e > 0.f) ? e : 0.2f * e;
            sp[lane][head] = __expf(e - mh) * ish;
        }
        __syncthreads();
        for (int t = 0; t < cnt; t++) {
            float x = feat[(size_t)su[t] * HID + tid];
            float4 p0 = *reinterpret_cast<const float4*>(&sp[t][0]);
            float4 p1 = *reinterpret_cast<const float4*>(&sp[t][4]);
            acc[0] += p0.x * x; acc[1] += p0.y * x;
            acc[2] += p0.z * x; acc[3] += p0.w * x;
            acc[4] += p1.x * x; acc[5] += p1.y * x;
            acc[6] += p1.z * x; acc[7] += p1.w * x;
        }
        __syncthreads();
    }
    size_t ob = (size_t)v * (HEADS * HID) + tid;
#pragma unroll
    for (int h = 0; h < 8; h++) out[ob + h * HID] = acc[h];
}

// permute w2 -> W2p[h*256+k][j] = w2[k][h*256+j] * (1/8)
__global__ void k_permw2(const float* __restrict__ w2, float* __restrict__ w2p) {
    int i = blockIdx.x * blockDim.x + threadIdx.x;   // over 2048*256
    if (i >= HEADS * HID * HID) return;
    int rowp = i >> 8;           // h*256+k
    int j = i & 255;
    int h = rowp >> 8, k = rowp & 255;
    w2p[i] = w2[(size_t)k * (HEADS * HID) + h * HID + j] * 0.125f;
}

// ------------------------- final tiny GEMM (N=2) ---------------------------
__global__ void k_final(const float* __restrict__ t1, const float* __restrict__ wc2,
                        const float* __restrict__ bc2, float* __restrict__ out) {
    __shared__ float w[256];
    if (threadIdx.x < 256) w[threadIdx.x] = wc2[threadIdx.x];
    __syncthreads();
    int row = blockIdx.x * blockDim.x + threadIdx.x;
    if (row >= N_NODES) return;
    float a0 = bc2[0], a1 = bc2[1];
    const float* t = t1 + (size_t)row * 128;
#pragma unroll 8
    for (int k = 0; k < 128; k++) {
        float x = t[k];
        a0 += x * w[2 * k];
        a1 += x * w[2 * k + 1];
    }
    out[row * 2 + 0] = a0;
    out[row * 2 + 1] = a1;
}

// ------------------------- host -------------------------
static inline int cdiv(int a, int b) { return (a + b - 1) / b; }

#define SMEM_BYTES (SMEM_FLOATS * 4)

extern "C" void kernel_launch(void* const* d_in, const int* in_sizes, int n_in,
                              void* d_out, int out_size) {
    const float* x     = (const float*)d_in[0];
    const int*   ei    = (const int*)  d_in[1];   // [2, E]
    const float* w_in  = (const float*)d_in[2];
    const float* b_in  = (const float*)d_in[3];
    const float* w0    = (const float*)d_in[4];
    const float* asrc0 = (const float*)d_in[5];
    const float* adst0 = (const float*)d_in[6];
    const float* b0    = (const float*)d_in[7];
    const float* w1    = (const float*)d_in[8];
    const float* asrc1 = (const float*)d_in[9];
    const float* adst1 = (const float*)d_in[10];
    const float* b1    = (const float*)d_in[11];
    const float* w2    = (const float*)d_in[12];
    const float* asrc2 = (const float*)d_in[13];
    const float* adst2 = (const float*)d_in[14];
    const float* b2    = (const float*)d_in[15];
    const float* wc1   = (const float*)d_in[16];
    const float* bc1   = (const float*)d_in[17];
    const float* wc2   = (const float*)d_in[18];
    const float* bc2   = (const float*)d_in[19];

    const int* src = ei;
    const int* dst = ei + E_EDGES;

    float *p_h, *p_h2, *p_big, *p_xp, *p_w2p, *p_cvec, *p_ssrc, *p_sdst, *p_t1;
    int *p_deg, *p_fill, *p_rowptr, *p_col, *p_bsum;
    cudaGetSymbolAddress((void**)&p_h, g_h);
    cudaGetSymbolAddress((void**)&p_h2, g_h2);
    cudaGetSymbolAddress((void**)&p_big, g_big);
    cudaGetSymbolAddress((void**)&p_xp, g_xp);
    cudaGetSymbolAddress((void**)&p_w2p, g_w2p);
    cudaGetSymbolAddress((void**)&p_cvec, g_cvec);
    cudaGetSymbolAddress((void**)&p_ssrc, g_ssrc);
    cudaGetSymbolAddress((void**)&p_sdst, g_sdst);
    cudaGetSymbolAddress((void**)&p_t1, g_t1);
    cudaGetSymbolAddress((void**)&p_deg, g_deg);
    cudaGetSymbolAddress((void**)&p_fill, g_fill);
    cudaGetSymbolAddress((void**)&p_rowptr, g_rowptr);
    cudaGetSymbolAddress((void**)&p_col, g_col);
    cudaGetSymbolAddress((void**)&p_bsum, g_bsum);

    // opt-in to >48KB dynamic smem for all GEMM instantiations (idempotent)
    cudaFuncSetAttribute(sgemm_tc<0, 0>, cudaFuncAttributeMaxDynamicSharedMemorySize, SMEM_BYTES);
    cudaFuncSetAttribute(sgemm_tc<0, 1>, cudaFuncAttributeMaxDynamicSharedMemorySize, SMEM_BYTES);
    cudaFuncSetAttribute(sgemm_tc<1, 0>, cudaFuncAttributeMaxDynamicSharedMemorySize, SMEM_BYTES);

    // ---- CSR build + preprocessing ----
    k_init_deg<<<cdiv(N_NODES, 256), 256>>>(p_deg, p_fill);
    k_hist<<<cdiv(E_EDGES, 256), 256>>>(dst, p_deg);
    k_scan1<<<NBLK, 1024>>>(p_deg, p_rowptr, p_bsum);
    k_scan2<<<1, 1>>>(p_bsum, p_rowptr);
    k_scan3<<<cdiv(N_NODES, 256), 256>>>(p_rowptr, p_bsum);
    k_fill<<<cdiv(TOT_E, 256), 256>>>(src, dst, p_rowptr, p_fill, p_col);
    k_padx<<<cdiv(N_NODES * KPAD, 256), 256>>>(x, p_xp);
    k_cvec<<<cdiv(HEADS * HID, 256), 256>>>(w2, asrc2, adst2, p_cvec);
    k_permw2<<<cdiv(HEADS * HID * HID, 256), 256>>>(w2, p_w2p);

    dim3 blk(256);
    int nWarpBlocks = cdiv(N_NODES * HEADS, 8);  // 8 warps / block

    // ---- input projection: h = xp @ w_in + b_in (K padded to 176) ----
    {
        dim3 grid(cdiv(HID, 128), cdiv(N_NODES, 128));
        sgemm_tc<0, 0><<<grid, blk, SMEM_BYTES>>>(p_xp, w_in, b_in, p_h, N_NODES, HID, KPAD,
                                                  nullptr, nullptr, nullptr, nullptr);
    }
    // ---- GAT layer 0 (concat); scores fused into GEMM epilogue ----
    {
        dim3 grid(cdiv(HID, 128), cdiv(N_NODES, 128));
        sgemm_tc<0, 1><<<grid, blk, SMEM_BYTES>>>(p_h, w0, nullptr, p_h2, N_NODES, HID, HID,
                                                  asrc0, adst0, p_ssrc, p_sdst);
        k_aggr<32><<<nWarpBlocks, 256>>>(p_h2, p_rowptr, p_col, p_ssrc, p_sdst, b0, p_h);
    }
    // ---- GAT layer 1 (concat); scores fused into GEMM epilogue ----
    {
        dim3 grid(cdiv(HID, 128), cdiv(N_NODES, 128));
        sgemm_tc<0, 1><<<grid, blk, SMEM_BYTES>>>(p_h, w1, nullptr, p_h2, N_NODES, HID, HID,
                                                  asrc1, adst1, p_ssrc, p_sdst);
        k_aggr<32><<<nWarpBlocks, 256>>>(p_h2, p_rowptr, p_col, p_ssrc, p_sdst, b1, p_h);
    }
    // ---- GAT layer 2 (mean heads), aggregation commuted before GEMM ----
    {
        k_scores2<<<cdiv(N_NODES * 32, 256), 256>>>(p_h, p_cvec, p_ssrc, p_sdst);
        k_aggr2c<<<N_NODES, 256>>>(p_h, p_rowptr, p_col, p_ssrc, p_sdst, p_big);
        dim3 grid(cdiv(HID, 128), cdiv(N_NODES, 128));
        sgemm_tc<0, 0><<<grid, blk, SMEM_BYTES>>>(p_big, p_w2p, b2, p_h2, N_NODES, HID, HEADS * HID,
                                                  nullptr, nullptr, nullptr, nullptr);
    }
    // ---- classifier ----
    {
        dim3 grid(1, cdiv(N_NODES, 128));
        sgemm_tc<1, 0><<<grid, blk, SMEM_BYTES>>>(p_h2, wc1, bc1, p_t1, N_NODES, 128, HID,
                                                  nullptr, nullptr, nullptr, nullptr);
        k_final<<<cdiv(N_NODES, 256), 256>>>(p_t1, wc2, bc2, (float*)d_out);
    }
}